// round 4
// baseline (speedup 1.0000x reference)
#include <cuda_runtime.h>

#define NQ 16
#define NL 4
#define BATCH 512
#define NACT 6

struct Cplx { float r, i; };

__device__ __forceinline__ Cplx cmul(Cplx a, Cplx b) {
    return { a.r * b.r - a.i * b.i, a.r * b.i + a.i * b.r };
}

// PennyLane Rot(phi, theta, omega) = RZ(omega) RY(theta) RZ(phi):
// m00 = e^{-i(phi+omega)/2} cos(t/2); m01 = -e^{+i(phi-omega)/2} sin(t/2)
// m10 = e^{-i(phi-omega)/2} sin(t/2); m11 = e^{+i(phi+omega)/2} cos(t/2)
__device__ __forceinline__ void rot_mat(float phi, float theta, float omega,
                                        Cplx& m00, Cplx& m01, Cplx& m10, Cplx& m11) {
    float s, c, sa, ca, sb, cb;
    __sincosf(0.5f * theta, &s, &c);
    __sincosf(0.5f * (phi + omega), &sa, &ca);
    __sincosf(0.5f * (phi - omega), &sb, &cb);
    m00 = {  c * ca, -c * sa };
    m01 = { -s * cb, -s * sb };
    m10 = {  s * cb, -s * sb };
    m11 = {  c * ca,  c * sa };
}

// Shared-memory gate table: 8 floats per (layer,qubit) gate
// order: m00.r m00.i m01.r m01.i m10.r m10.i m11.r m11.i
__device__ __forceinline__ void smem_rot(const float* __restrict__ rot, int layer, int g,
                                         Cplx& m00, Cplx& m01, Cplx& m10, Cplx& m11) {
    const float* p = rot + (layer * NQ + g) * 8;
    m00 = { p[0], p[1] };  m01 = { p[2], p[3] };
    m10 = { p[4], p[5] };  m11 = { p[6], p[7] };
}

// Gate on register bit0 of k (local qubit l3 = global q): pairs (0,1),(2,3)
__device__ __forceinline__ void reg_gate0(float re[4], float im[4],
                                          Cplx m00, Cplx m01, Cplx m10, Cplx m11) {
#pragma unroll
    for (int base = 0; base < 4; base += 2) {
        float a0r = re[base], a0i = im[base];
        float a1r = re[base + 1], a1i = im[base + 1];
        re[base]     = m00.r * a0r - m00.i * a0i + m01.r * a1r - m01.i * a1i;
        im[base]     = m00.r * a0i + m00.i * a0r + m01.r * a1i + m01.i * a1r;
        re[base + 1] = m10.r * a0r - m10.i * a0i + m11.r * a1r - m11.i * a1i;
        im[base + 1] = m10.r * a0i + m10.i * a0r + m11.r * a1i + m11.i * a1r;
    }
}

// Gate on register bit1 of k (local qubit l4 = global q+1): pairs (0,2),(1,3)
__device__ __forceinline__ void reg_gate1(float re[4], float im[4],
                                          Cplx m00, Cplx m01, Cplx m10, Cplx m11) {
#pragma unroll
    for (int base = 0; base < 2; base++) {
        float a0r = re[base], a0i = im[base];
        float a1r = re[base + 2], a1i = im[base + 2];
        re[base]     = m00.r * a0r - m00.i * a0i + m01.r * a1r - m01.i * a1i;
        im[base]     = m00.r * a0i + m00.i * a0r + m01.r * a1i + m01.i * a1r;
        re[base + 2] = m10.r * a0r - m10.i * a0i + m11.r * a1r - m11.i * a1i;
        im[base + 2] = m10.r * a0i + m10.i * a0r + m11.r * a1i + m11.i * a1r;
    }
}

// Gate on lane bit t (butterfly exchange with partner lane)
__device__ __forceinline__ void shfl_gate(float re[4], float im[4], int lane, int t,
                                          Cplx m00, Cplx m01, Cplx m10, Cplx m11) {
    int myb = (lane >> t) & 1;
    Cplx ca = myb ? m11 : m00;   // coefficient of own amplitude
    Cplx cb = myb ? m10 : m01;   // coefficient of partner amplitude
#pragma unroll
    for (int k = 0; k < 4; k++) {
        float orr = __shfl_xor_sync(0xFFFFFFFFu, re[k], 1 << t);
        float oii = __shfl_xor_sync(0xFFFFFFFFu, im[k], 1 << t);
        float nr = ca.r * re[k] - ca.i * im[k] + cb.r * orr - cb.i * oii;
        float ni = ca.r * im[k] + ca.i * re[k] + cb.r * oii + cb.i * orr;
        re[k] = nr; im[k] = ni;
    }
}

// CZ chain phase: sign = (-1)^{popc(b & (b>>1) & mask)}, b = 7-bit local index
__device__ __forceinline__ void apply_cz(float re[4], float im[4], int bl, int mask) {
#pragma unroll
    for (int k = 0; k < 4; k++) {
        int b = bl | ((k & 1) << 3) | ((k >> 1) << 4);
        if (__popc(b & (b >> 1) & mask) & 1) { re[k] = -re[k]; im[k] = -im[k]; }
    }
}

// One CTA per sample: 16 warps compute the 16 qubit light cones, then a fused
// 16->6 FC epilogue. Gate matrices and embedding sincos are built cooperatively
// in shared memory once per CTA.
//
// Cone local-qubit layout: 7 local qubits l=0..6 map to global q-3..q+3.
//   l3 -> reg k bit0, l4 -> reg k bit1
//   l1 -> lane bit0, l2 -> lane bit1, l5 -> lane bit2, l0 -> lane bit3, l6 -> lane bit4
__global__ void __launch_bounds__(512)
fused_kernel(const float* __restrict__ x, const float* __restrict__ w,
             const float* __restrict__ fc_w, const float* __restrict__ fc_b,
             float* __restrict__ out) {
    __shared__ float rot[NL * NQ * 8];  // 64 gates x 8 floats = 2 KB
    __shared__ float xc[NQ], xs[NQ];    // cos/sin of x_q / 2
    __shared__ float z[NQ];

    int s    = blockIdx.x;
    int tid  = threadIdx.x;
    int wid  = tid >> 5;    // qubit index q = 0..15
    int lane = tid & 31;

    // ---- cooperative prologue ----
    if (tid < NL * NQ) {
        const float* p = w + tid * 3;   // w[layer][qubit][3], gate id = layer*16+qubit
        Cplx m00, m01, m10, m11;
        rot_mat(p[0], p[1], p[2], m00, m01, m10, m11);
        float* o = rot + tid * 8;
        o[0] = m00.r; o[1] = m00.i; o[2] = m01.r; o[3] = m01.i;
        o[4] = m10.r; o[5] = m10.i; o[6] = m11.r; o[7] = m11.i;
    } else if (tid < NL * NQ + NQ) {
        int g = tid - NL * NQ;
        float sx, cx;
        __sincosf(0.5f * x[s * NQ + g], &sx, &cx);
        xc[g] = cx; xs[g] = sx;
    }
    __syncthreads();

    int q = wid;

    // lane-bit contribution to the 7-bit local index
    int bl = ((lane >> 3) & 1)        // l0 at pos 0
           | ((lane & 1) << 1)        // l1 at pos 1
           | (((lane >> 1) & 1) << 2) // l2 at pos 2
           | (((lane >> 2) & 1) << 5) // l5 at pos 5
           | (((lane >> 4) & 1) << 6);// l6 at pos 6

    // ---- init: product state after RY(x) then Rot(layer0) ----
    // v = Rot0(g) @ (cos(x/2), sin(x/2)); virtual qubits -> (1,0)
    Cplx pre = { 1.f, 0.f };
    const int lane_locals[5] = { 1, 2, 5, 0, 6 };
#pragma unroll
    for (int t = 0; t < 5; t++) {
        int l = lane_locals[t];
        int g = q - 3 + l;
        Cplx v0 = { 1.f, 0.f }, v1 = { 0.f, 0.f };
        if (g >= 0 && g < NQ) {
            float cx = xc[g], sx = xs[g];
            Cplx m00, m01, m10, m11;
            smem_rot(rot, 0, g, m00, m01, m10, m11);
            v0 = { m00.r * cx + m01.r * sx, m00.i * cx + m01.i * sx };
            v1 = { m10.r * cx + m11.r * sx, m10.i * cx + m11.i * sx };
        }
        Cplx vv = ((lane >> t) & 1) ? v1 : v0;
        pre = cmul(pre, vv);
    }
    // register qubits l3 (g=q, always valid) and l4 (g=q+1)
    Cplx v30, v31, v40 = { 1.f, 0.f }, v41 = { 0.f, 0.f };
    {
        float cx = xc[q], sx = xs[q];
        Cplx m00, m01, m10, m11;
        smem_rot(rot, 0, q, m00, m01, m10, m11);
        v30 = { m00.r * cx + m01.r * sx, m00.i * cx + m01.i * sx };
        v31 = { m10.r * cx + m11.r * sx, m10.i * cx + m11.i * sx };
    }
    if (q + 1 < NQ) {
        float cx = xc[q + 1], sx = xs[q + 1];
        Cplx m00, m01, m10, m11;
        smem_rot(rot, 0, q + 1, m00, m01, m10, m11);
        v40 = { m00.r * cx + m01.r * sx, m00.i * cx + m01.i * sx };
        v41 = { m10.r * cx + m11.r * sx, m10.i * cx + m11.i * sx };
    }
    float re[4], im[4];
    {
        Cplx p0 = cmul(pre, v30), p1 = cmul(pre, v31);
        Cplx a0 = cmul(p0, v40), a1 = cmul(p1, v40);
        Cplx a2 = cmul(p0, v41), a3 = cmul(p1, v41);
        re[0] = a0.r; im[0] = a0.i;  re[1] = a1.r; im[1] = a1.i;
        re[2] = a2.r; im[2] = a2.i;  re[3] = a3.r; im[3] = a3.i;
    }

    Cplx m00, m01, m10, m11;

    // C1: surviving CZ pairs on local qubits 0..6
    apply_cz(re, im, bl, 0x3F);

    // Layer 1 Rot on q-2..q+2
    if (q - 2 >= 0)  { smem_rot(rot, 1, q - 2, m00, m01, m10, m11); shfl_gate(re, im, lane, 0, m00, m01, m10, m11); }
    if (q - 1 >= 0)  { smem_rot(rot, 1, q - 1, m00, m01, m10, m11); shfl_gate(re, im, lane, 1, m00, m01, m10, m11); }
    smem_rot(rot, 1, q, m00, m01, m10, m11); reg_gate0(re, im, m00, m01, m10, m11);
    if (q + 1 < NQ)  { smem_rot(rot, 1, q + 1, m00, m01, m10, m11); reg_gate1(re, im, m00, m01, m10, m11); }
    if (q + 2 < NQ)  { smem_rot(rot, 1, q + 2, m00, m01, m10, m11); shfl_gate(re, im, lane, 2, m00, m01, m10, m11); }

    // C2: surviving pairs l=1..4
    apply_cz(re, im, bl, 0x1E);

    // Layer 2 Rot on q-1..q+1
    if (q - 1 >= 0)  { smem_rot(rot, 2, q - 1, m00, m01, m10, m11); shfl_gate(re, im, lane, 1, m00, m01, m10, m11); }
    smem_rot(rot, 2, q, m00, m01, m10, m11); reg_gate0(re, im, m00, m01, m10, m11);
    if (q + 1 < NQ)  { smem_rot(rot, 2, q + 1, m00, m01, m10, m11); reg_gate1(re, im, m00, m01, m10, m11); }

    // C3: surviving pairs l=2,3
    apply_cz(re, im, bl, 0x0C);

    // Layer 3 Rot on q only
    smem_rot(rot, 3, q, m00, m01, m10, m11); reg_gate0(re, im, m00, m01, m10, m11);

    // ---- readout: <Z_q> = sum_b (-1)^{b_{l3}} |amp|^2 ; l3 = reg k bit0 ----
    float zp = 0.f;
#pragma unroll
    for (int k = 0; k < 4; k++) {
        float p = re[k] * re[k] + im[k] * im[k];
        zp += (k & 1) ? -p : p;
    }
#pragma unroll
    for (int off = 16; off; off >>= 1)
        zp += __shfl_xor_sync(0xFFFFFFFFu, zp, off);

    if (lane == 0) z[wid] = zp;
    __syncthreads();

    // FC: 6 outputs, one thread each
    if (tid < NACT) {
        int a = tid;
        float acc = fc_b[a];
#pragma unroll
        for (int j = 0; j < NQ; j++)
            acc += z[j] * fc_w[a * NQ + j];
        out[s * NACT + a] = acc;
    }
}

extern "C" void kernel_launch(void* const* d_in, const int* in_sizes, int n_in,
                              void* d_out, int out_size) {
    (void)in_sizes; (void)n_in; (void)out_size;
    const float* x    = (const float*)d_in[0];  // [512,16]
    const float* w    = (const float*)d_in[1];  // [4,16,3]
    const float* fc_w = (const float*)d_in[2];  // [6,16]
    const float* fc_b = (const float*)d_in[3];  // [6]
    float* out = (float*)d_out;                 // [512,6]

    fused_kernel<<<BATCH, 512>>>(x, w, fc_w, fc_b, out);
}

// round 9
// speedup vs baseline: 1.2113x; 1.2113x over previous
#include <cuda_runtime.h>

#define NQ 16
#define NL 4
#define BATCH 512
#define NACT 6
#define GP 22   // padded qubit slots: global g in [-3,18] -> gp = g+3 in [0,22)

struct Cplx { float r, i; };

__device__ __forceinline__ Cplx cmul(Cplx a, Cplx b) {
    return { a.r * b.r - a.i * b.i, a.r * b.i + a.i * b.r };
}

// PennyLane Rot(phi, theta, omega) = RZ(omega) RY(theta) RZ(phi):
// m00 = e^{-i(phi+omega)/2} cos(t/2); m01 = -e^{+i(phi-omega)/2} sin(t/2)
// m10 = e^{-i(phi-omega)/2} sin(t/2); m11 = e^{+i(phi+omega)/2} cos(t/2)
__device__ __forceinline__ void rot_mat(float phi, float theta, float omega,
                                        Cplx& m00, Cplx& m01, Cplx& m10, Cplx& m11) {
    float s, c, sa, ca, sb, cb;
    __sincosf(0.5f * theta, &s, &c);
    __sincosf(0.5f * (phi + omega), &sa, &ca);
    __sincosf(0.5f * (phi - omega), &sb, &cb);
    m00 = {  c * ca, -c * sa };
    m01 = { -s * cb, -s * sb };
    m10 = {  s * cb, -s * sb };
    m11 = {  c * ca,  c * sa };
}

// Gate table entry: 2 float4 per gate: (m00.r m00.i m01.r m01.i) (m10.r m10.i m11.r m11.i)
__device__ __forceinline__ void load_gate(const float4* __restrict__ rotx, int layer, int gp,
                                          Cplx& m00, Cplx& m01, Cplx& m10, Cplx& m11) {
    float4 a = rotx[(layer * GP + gp) * 2];
    float4 b = rotx[(layer * GP + gp) * 2 + 1];
    m00 = { a.x, a.y };  m01 = { a.z, a.w };
    m10 = { b.x, b.y };  m11 = { b.z, b.w };
}

// Gate on register bit0 of k (local qubit l3 = global q): pairs (0,1),(2,3)
__device__ __forceinline__ void reg_gate0(float re[4], float im[4],
                                          Cplx m00, Cplx m01, Cplx m10, Cplx m11) {
#pragma unroll
    for (int base = 0; base < 4; base += 2) {
        float a0r = re[base], a0i = im[base];
        float a1r = re[base + 1], a1i = im[base + 1];
        re[base]     = m00.r * a0r - m00.i * a0i + m01.r * a1r - m01.i * a1i;
        im[base]     = m00.r * a0i + m00.i * a0r + m01.r * a1i + m01.i * a1r;
        re[base + 1] = m10.r * a0r - m10.i * a0i + m11.r * a1r - m11.i * a1i;
        im[base + 1] = m10.r * a0i + m10.i * a0r + m11.r * a1i + m11.i * a1r;
    }
}

// Gate on register bit1 of k (local qubit l4 = global q+1): pairs (0,2),(1,3)
__device__ __forceinline__ void reg_gate1(float re[4], float im[4],
                                          Cplx m00, Cplx m01, Cplx m10, Cplx m11) {
#pragma unroll
    for (int base = 0; base < 2; base++) {
        float a0r = re[base], a0i = im[base];
        float a1r = re[base + 2], a1i = im[base + 2];
        re[base]     = m00.r * a0r - m00.i * a0i + m01.r * a1r - m01.i * a1i;
        im[base]     = m00.r * a0i + m00.i * a0r + m01.r * a1i + m01.i * a1r;
        re[base + 2] = m10.r * a0r - m10.i * a0i + m11.r * a1r - m11.i * a1i;
        im[base + 2] = m10.r * a0i + m10.i * a0r + m11.r * a1i + m11.i * a1r;
    }
}

// Gate on lane bit t (butterfly exchange with partner lane)
__device__ __forceinline__ void shfl_gate(float re[4], float im[4], int lane, int t,
                                          Cplx m00, Cplx m01, Cplx m10, Cplx m11) {
    int myb = (lane >> t) & 1;
    Cplx ca = myb ? m11 : m00;   // coefficient of own amplitude
    Cplx cb = myb ? m10 : m01;   // coefficient of partner amplitude
#pragma unroll
    for (int k = 0; k < 4; k++) {
        float orr = __shfl_xor_sync(0xFFFFFFFFu, re[k], 1 << t);
        float oii = __shfl_xor_sync(0xFFFFFFFFu, im[k], 1 << t);
        float nr = ca.r * re[k] - ca.i * im[k] + cb.r * orr - cb.i * oii;
        float ni = ca.r * im[k] + ca.i * re[k] + cb.r * oii + cb.i * orr;
        re[k] = nr; im[k] = ni;
    }
}

// CZ chain phase: sign = (-1)^{popc(b & (b>>1) & mask)}, b = 7-bit local index
__device__ __forceinline__ void apply_cz(float re[4], float im[4], int bl, int mask) {
#pragma unroll
    for (int k = 0; k < 4; k++) {
        int b = bl | ((k & 1) << 3) | ((k >> 1) << 4);
        if (__popc(b & (b >> 1) & mask) & 1) { re[k] = -re[k]; im[k] = -im[k]; }
    }
}

// One CTA per sample: 16 warps compute the 16 qubit light cones (straight-line,
// identity-padded gate table -> no branches), then a fused 16->6 FC epilogue.
//
// Cone local-qubit layout: 7 local qubits l=0..6 map to global q-3..q+3.
//   l3 -> reg k bit0, l4 -> reg k bit1
//   l1 -> lane bit0, l2 -> lane bit1, l5 -> lane bit2, l0 -> lane bit3, l6 -> lane bit4
__global__ void __launch_bounds__(512)
fused_kernel(const float* __restrict__ x, const float* __restrict__ w,
             const float* __restrict__ fc_w, const float* __restrict__ fc_b,
             float* __restrict__ out) {
    __shared__ float4 rotx[NL * GP * 2];  // padded gate table, identity outside [0,16)
    __shared__ float4 u[GP];              // init vectors (u0.r,u0.i,u1.r,u1.i), (1,0,0,0) padding
    __shared__ float z[NQ];

    int s    = blockIdx.x;
    int tid  = threadIdx.x;
    int wid  = tid >> 5;    // qubit index q = 0..15
    int lane = tid & 31;

    // ---- cooperative prologue ----
    if (tid < NL * GP) {                 // 88 threads: gate table
        int layer = tid / GP, gp = tid % GP, g = gp - 3;
        Cplx m00 = {1.f,0.f}, m01 = {0.f,0.f}, m10 = {0.f,0.f}, m11 = {1.f,0.f};
        if (g >= 0 && g < NQ) {
            const float* p = w + (layer * NQ + g) * 3;
            rot_mat(p[0], p[1], p[2], m00, m01, m10, m11);
        }
        rotx[tid * 2]     = { m00.r, m00.i, m01.r, m01.i };
        rotx[tid * 2 + 1] = { m10.r, m10.i, m11.r, m11.i };
    } else if (tid < NL * GP + GP) {     // 22 threads: init vectors
        int gp = tid - NL * GP, g = gp - 3;
        float4 v = { 1.f, 0.f, 0.f, 0.f };
        if (g >= 0 && g < NQ) {
            float sx, cx;
            __sincosf(0.5f * x[s * NQ + g], &sx, &cx);
            Cplx m00, m01, m10, m11;
            const float* p = w + g * 3;  // layer 0
            rot_mat(p[0], p[1], p[2], m00, m01, m10, m11);
            v = { m00.r * cx + m01.r * sx, m00.i * cx + m01.i * sx,
                  m10.r * cx + m11.r * sx, m10.i * cx + m11.i * sx };
        }
        u[gp] = v;
    }
    __syncthreads();

    int q = wid;

    // lane-bit contribution to the 7-bit local index
    int bl = ((lane >> 3) & 1)        // l0 at pos 0
           | ((lane & 1) << 1)        // l1 at pos 1
           | (((lane >> 1) & 1) << 2) // l2 at pos 2
           | (((lane >> 2) & 1) << 5) // l5 at pos 5
           | (((lane >> 4) & 1) << 6);// l6 at pos 6

    // ---- init: product of precomputed u vectors over the 5 lane qubits ----
    // lane qubit t holds local qubit lane_locals[t]; padded slot index gp = q + l.
    Cplx pre = { 1.f, 0.f };
    const int lane_locals[5] = { 1, 2, 5, 0, 6 };
#pragma unroll
    for (int t = 0; t < 5; t++) {
        float4 v = u[q + lane_locals[t]];       // warp-uniform LDS.128
        Cplx vv = ((lane >> t) & 1) ? Cplx{ v.z, v.w } : Cplx{ v.x, v.y };
        pre = cmul(pre, vv);
    }
    // register qubits l3 (gp=q+3) and l4 (gp=q+4)
    float re[4], im[4];
    {
        float4 a = u[q + 3];
        float4 b = u[q + 4];
        Cplx p0 = cmul(pre, { a.x, a.y }), p1 = cmul(pre, { a.z, a.w });
        Cplx a0 = cmul(p0, { b.x, b.y }), a1 = cmul(p1, { b.x, b.y });
        Cplx a2 = cmul(p0, { b.z, b.w }), a3 = cmul(p1, { b.z, b.w });
        re[0] = a0.r; im[0] = a0.i;  re[1] = a1.r; im[1] = a1.i;
        re[2] = a2.r; im[2] = a2.i;  re[3] = a3.r; im[3] = a3.i;
    }

    Cplx m00, m01, m10, m11;

    // C1: surviving CZ pairs on local qubits 0..6
    apply_cz(re, im, bl, 0x3F);

    // Layer 1 Rot on q-2..q+2 (identity-padded -> unconditional)
    load_gate(rotx, 1, q + 1, m00, m01, m10, m11); shfl_gate(re, im, lane, 0, m00, m01, m10, m11); // q-2 (l1)
    load_gate(rotx, 1, q + 2, m00, m01, m10, m11); shfl_gate(re, im, lane, 1, m00, m01, m10, m11); // q-1 (l2)
    load_gate(rotx, 1, q + 3, m00, m01, m10, m11); reg_gate0(re, im, m00, m01, m10, m11);          // q   (l3)
    load_gate(rotx, 1, q + 4, m00, m01, m10, m11); reg_gate1(re, im, m00, m01, m10, m11);          // q+1 (l4)
    load_gate(rotx, 1, q + 5, m00, m01, m10, m11); shfl_gate(re, im, lane, 2, m00, m01, m10, m11); // q+2 (l5)

    // C2: surviving pairs l=1..4
    apply_cz(re, im, bl, 0x1E);

    // Layer 2 Rot on q-1..q+1
    load_gate(rotx, 2, q + 2, m00, m01, m10, m11); shfl_gate(re, im, lane, 1, m00, m01, m10, m11); // q-1 (l2)
    load_gate(rotx, 2, q + 3, m00, m01, m10, m11); reg_gate0(re, im, m00, m01, m10, m11);          // q   (l3)
    load_gate(rotx, 2, q + 4, m00, m01, m10, m11); reg_gate1(re, im, m00, m01, m10, m11);          // q+1 (l4)

    // C3: surviving pairs l=2,3
    apply_cz(re, im, bl, 0x0C);

    // Layer 3 Rot on q only
    load_gate(rotx, 3, q + 3, m00, m01, m10, m11); reg_gate0(re, im, m00, m01, m10, m11);

    // ---- readout: <Z_q> = sum_b (-1)^{b_{l3}} |amp|^2 ; l3 = reg k bit0 ----
    float zp = 0.f;
#pragma unroll
    for (int k = 0; k < 4; k++) {
        float p = re[k] * re[k] + im[k] * im[k];
        zp += (k & 1) ? -p : p;
    }
#pragma unroll
    for (int off = 16; off; off >>= 1)
        zp += __shfl_xor_sync(0xFFFFFFFFu, zp, off);

    if (lane == 0) z[wid] = zp;
    __syncthreads();

    // FC: 6 outputs, one thread each
    if (tid < NACT) {
        int a = tid;
        float acc = fc_b[a];
#pragma unroll
        for (int j = 0; j < NQ; j++)
            acc += z[j] * fc_w[a * NQ + j];
        out[s * NACT + a] = acc;
    }
}

extern "C" void kernel_launch(void* const* d_in, const int* in_sizes, int n_in,
                              void* d_out, int out_size) {
    (void)in_sizes; (void)n_in; (void)out_size;
    const float* x    = (const float*)d_in[0];  // [512,16]
    const float* w    = (const float*)d_in[1];  // [4,16,3]
    const float* fc_w = (const float*)d_in[2];  // [6,16]
    const float* fc_b = (const float*)d_in[3];  // [6]
    float* out = (float*)d_out;                 // [512,6]

    fused_kernel<<<BATCH, 512>>>(x, w, fc_w, fc_b, out);
}